// round 7
// baseline (speedup 1.0000x reference)
#include <cuda_runtime.h>
#include <math.h>

#define NLOC 1940
#define NPRI 8732
#define BATCH 16
#define TOPK 10
#define NOBJ (BATCH*TOPK)
#define DS 64          // decoded image size
#define IMG 300
#define ZWHAT 64
#define CPAD 4         // padded channel count (3 used + 1 pad) -> 16B/pixel
#define TILE 16        // composite tile edge
#define NTX ((IMG + TILE - 1) / TILE)   // 19

// scratch (device globals; no allocation allowed)
__device__ float g_decoded[NOBJ * CPAD * DS * DS];   // [obj][pix][4], 10.5 MB
__device__ int   g_order[BATCH * TOPK];

// ---------------------------------------------------------------------------
// f32x2 packed-math helpers (sm_103a FFMA2 path; ptxas won't auto-fuse)
// ---------------------------------------------------------------------------
__device__ __forceinline__ unsigned long long pack2(float lo, float hi) {
    unsigned long long r;
    asm("mov.b64 %0, {%1, %2};" : "=l"(r) : "f"(lo), "f"(hi));
    return r;
}
__device__ __forceinline__ void unpack2(unsigned long long v, float& a, float& b) {
    asm("mov.b64 {%0, %1}, %2;" : "=f"(a), "=f"(b) : "l"(v));
}
__device__ __forceinline__ unsigned long long ffma2(unsigned long long a,
                                                    unsigned long long b,
                                                    unsigned long long c) {
    unsigned long long d;
    asm("fma.rn.f32x2 %0, %1, %2, %3;" : "=l"(d) : "l"(a), "l"(b), "l"(c));
    return d;
}

// prior index -> location index (closed form of _recon_indices)
__device__ __forceinline__ int prior_to_loc(int i) {
    if (i < 5776) return i >> 2;
    if (i < 7942) return 1444 + (i - 5776) / 6;
    if (i < 8542) return 1805 + (i - 7942) / 6;
    if (i < 8692) return 1905 + (i - 8542) / 6;
    if (i < 8728) return 1930 + ((i - 8692) >> 2);
    return 1939;
}
__device__ __forceinline__ void loc_to_priors(int l, int& start, int& bpl) {
    if (l < 1444)      { start = 4 * l;                 bpl = 4; }
    else if (l < 1805) { start = 5776 + 6 * (l - 1444); bpl = 6; }
    else if (l < 1905) { start = 7942 + 6 * (l - 1805); bpl = 6; }
    else if (l < 1930) { start = 8542 + 6 * (l - 1905); bpl = 6; }
    else               { start = 8692 + 4 * (l - 1930); bpl = 4; }
}
__device__ __forceinline__ bool better(float a, int ia, float b, int ib) {
    return a > b || (a == b && ia < ib);
}
__device__ __forceinline__ void insert3(float v, int i,
                                        float& v0, int& i0, float& v1, int& i1,
                                        float& v2, int& i2) {
    if (better(v, i, v0, i0)) { v2 = v1; i2 = i1; v1 = v0; i1 = i0; v0 = v; i0 = i; }
    else if (better(v, i, v1, i1)) { v2 = v1; i2 = i1; v1 = v; i1 = i; }
    else if (better(v, i, v2, i2)) { v2 = v; i2 = i; }
}

// block-redundant top-3 locations of batch b; returns prior index of rank j.
__device__ __forceinline__ int block_topk(const float* __restrict__ z_depth,
                                          int b, int j, float* scratch) {
    const int tid = threadIdx.x;
    float (*sv)[3] = (float(*)[3])scratch;
    int   (*si)[3] = (int(*)[3])(scratch + 256 * 3);

    float v0 = -INFINITY, v1 = -INFINITY, v2 = -INFINITY;
    int   i0 = 0x7fffffff, i1 = 0x7fffffff, i2 = 0x7fffffff;
    const float4* __restrict__ zd4 =
        reinterpret_cast<const float4*>(z_depth + b * NLOC);
    for (int i = tid; i < NLOC / 4; i += 256) {
        const float4 v = __ldg(zd4 + i);
        insert3(v.x, 4 * i + 0, v0, i0, v1, i1, v2, i2);
        insert3(v.y, 4 * i + 1, v0, i0, v1, i1, v2, i2);
        insert3(v.z, 4 * i + 2, v0, i0, v1, i1, v2, i2);
        insert3(v.w, 4 * i + 3, v0, i0, v1, i1, v2, i2);
    }
    sv[tid][0] = v0; sv[tid][1] = v1; sv[tid][2] = v2;
    si[tid][0] = i0; si[tid][1] = i1; si[tid][2] = i2;
    __syncthreads();
    for (int s = 128; s > 0; s >>= 1) {
        if (tid < s) {
            #pragma unroll
            for (int q = 0; q < 3; q++)
                insert3(sv[tid + s][q], si[tid + s][q], v0, i0, v1, i1, v2, i2);
            sv[tid][0] = v0; sv[tid][1] = v1; sv[tid][2] = v2;
            si[tid][0] = i0; si[tid][1] = i1; si[tid][2] = i2;
        }
        __syncthreads();
    }
    __shared__ int s_ord;
    if (tid == 0) {
        int ranks[3] = { i0, i1, i2 };
        int ord = -1, cnt = 0;
        #pragma unroll
        for (int r = 0; r < 3; r++) {
            int start, bpl;
            loc_to_priors(ranks[r], start, bpl);
            if (ord < 0 && j < cnt + bpl) ord = start + (j - cnt);
            cnt += bpl;
        }
        s_ord = ord;
    }
    __syncthreads();
    return s_ord;
}

// ---------------------------------------------------------------------------
// Register-tiled deconv layer with PF-deep register-pipelined weight prefetch.
// Thread owns (o = t%CO, row y = t/CO): all W pixels of that row.
// Steady-state MLP ~= PF on the weight stream.
// deconv2x2 stride 2: out[o,2y+a,2x+b] = bias[o] + sum_c in[c,y,x]*W[c,o,a,b]
// ---------------------------------------------------------------------------
template<int CI, int CO, int H, int W, int PF>
__device__ __forceinline__ void dlayer_t(const float* __restrict__ in,
                                         float* __restrict__ out,
                                         const float* __restrict__ Wt,
                                         const float* __restrict__ bias)
{
    static_assert(CO * H == 256, "thread mapping");
    static_assert(CI % PF == 0, "prefetch depth");
    constexpr int HW = H * W;
    const int o = threadIdx.x % CO;
    const int y = threadIdx.x / CO;
    const float4* __restrict__ W4 = reinterpret_cast<const float4*>(Wt) + o;
    const float bo = __ldg(bias + o);
    float* orow0 = out + (o * 2 * H + 2 * y) * (2 * W);
    float* orow1 = orow0 + 2 * W;

    float4 wbuf[PF];
    #pragma unroll
    for (int i = 0; i < PF; i++) wbuf[i] = __ldg(W4 + i * CO);

    if constexpr (W == 1) {
        float a0 = bo, a1 = bo, a2 = bo, a3 = bo;
        for (int c = 0; c < CI; c += PF) {
            #pragma unroll
            for (int i = 0; i < PF; i++) {
                const float4 wv = wbuf[i];
                const int nc = c + i + PF;
                if (nc < CI) wbuf[i] = __ldg(W4 + nc * CO);
                const float iv = in[c + i];
                a0 = fmaf(iv, wv.x, a0);
                a1 = fmaf(iv, wv.y, a1);
                a2 = fmaf(iv, wv.z, a2);
                a3 = fmaf(iv, wv.w, a3);
            }
        }
        orow0[0] = fmaxf(a0, 0.f); orow0[1] = fmaxf(a1, 0.f);
        orow1[0] = fmaxf(a2, 0.f); orow1[1] = fmaxf(a3, 0.f);
    } else {
        constexpr int NP = W / 2;   // pixel pairs in the row
        unsigned long long acc[4][NP];
        const unsigned long long bb = pack2(bo, bo);
        #pragma unroll
        for (int q = 0; q < 4; q++)
            #pragma unroll
            for (int pp = 0; pp < NP; pp++) acc[q][pp] = bb;

        const float* iprow = in + y * W;
        for (int c = 0; c < CI; c += PF) {
            #pragma unroll
            for (int i = 0; i < PF; i++) {
                const float4 wv = wbuf[i];
                const int nc = c + i + PF;
                if (nc < CI) wbuf[i] = __ldg(W4 + nc * CO);
                const unsigned long long w0 = pack2(wv.x, wv.x);
                const unsigned long long w1 = pack2(wv.y, wv.y);
                const unsigned long long w2 = pack2(wv.z, wv.z);
                const unsigned long long w3 = pack2(wv.w, wv.w);
                const unsigned long long* iv2 =
                    reinterpret_cast<const unsigned long long*>(iprow + (c + i) * HW);
                #pragma unroll
                for (int pp = 0; pp < NP; pp++) {
                    const unsigned long long iv = iv2[pp];
                    acc[0][pp] = ffma2(iv, w0, acc[0][pp]);
                    acc[1][pp] = ffma2(iv, w1, acc[1][pp]);
                    acc[2][pp] = ffma2(iv, w2, acc[2][pp]);
                    acc[3][pp] = ffma2(iv, w3, acc[3][pp]);
                }
            }
        }
        #pragma unroll
        for (int pp = 0; pp < NP; pp++) {
            float a0l, a0h, a1l, a1h, a2l, a2h, a3l, a3h;
            unpack2(acc[0][pp], a0l, a0h); unpack2(acc[1][pp], a1l, a1h);
            unpack2(acc[2][pp], a2l, a2h); unpack2(acc[3][pp], a3l, a3h);
            const float4 r0 = make_float4(fmaxf(a0l, 0.f), fmaxf(a1l, 0.f),
                                          fmaxf(a0h, 0.f), fmaxf(a1h, 0.f));
            const float4 r1 = make_float4(fmaxf(a2l, 0.f), fmaxf(a3l, 0.f),
                                          fmaxf(a2h, 0.f), fmaxf(a3h, 0.f));
            *reinterpret_cast<float4*>(orow0 + 4 * pp) = r0;
            *reinterpret_cast<float4*>(orow1 + 4 * pp) = r1;
        }
    }
}

// Final layer: ci=16, co=3, 32x32 -> 64x64, sigmoid, CPAD-interleaved output.
// Thread owns 4 src pixels (all 3 channels) -> 16 float4 texel stores.
// sw: 195 floats staged in smem: W5 (192) + b5 (3).
__device__ __forceinline__ void final_layer(const float* __restrict__ in,
                                            const float* __restrict__ sw,
                                            float* __restrict__ gout)
{
    const int tid = threadIdx.x;
    const int pbase = tid * 4;
    const int sy = pbase >> 5;      // src row in 32x32
    const int sx = pbase & 31;      // src col (multiple of 4)

    unsigned long long acc[3][4][2];
    #pragma unroll
    for (int o = 0; o < 3; o++) {
        const unsigned long long bb = pack2(sw[192 + o], sw[192 + o]);
        #pragma unroll
        for (int q = 0; q < 4; q++) { acc[o][q][0] = bb; acc[o][q][1] = bb; }
    }

    #pragma unroll 4
    for (int c = 0; c < 16; c++) {
        const unsigned long long* iv2 =
            reinterpret_cast<const unsigned long long*>(in + c * 1024 + pbase);
        const unsigned long long i0 = iv2[0], i1 = iv2[1];
        #pragma unroll
        for (int o = 0; o < 3; o++) {
            const float4 wv = *reinterpret_cast<const float4*>(sw + (c * 3 + o) * 4);
            const unsigned long long w0 = pack2(wv.x, wv.x);
            const unsigned long long w1 = pack2(wv.y, wv.y);
            const unsigned long long w2 = pack2(wv.z, wv.z);
            const unsigned long long w3 = pack2(wv.w, wv.w);
            acc[o][0][0] = ffma2(i0, w0, acc[o][0][0]);
            acc[o][0][1] = ffma2(i1, w0, acc[o][0][1]);
            acc[o][1][0] = ffma2(i0, w1, acc[o][1][0]);
            acc[o][1][1] = ffma2(i1, w1, acc[o][1][1]);
            acc[o][2][0] = ffma2(i0, w2, acc[o][2][0]);
            acc[o][2][1] = ffma2(i1, w2, acc[o][2][1]);
            acc[o][3][0] = ffma2(i0, w3, acc[o][3][0]);
            acc[o][3][1] = ffma2(i1, w3, acc[o][3][1]);
        }
    }

    float4* g4 = reinterpret_cast<float4*>(gout);
    #pragma unroll
    for (int pp = 0; pp < 2; pp++) {
        #pragma unroll
        for (int e = 0; e < 2; e++) {
            const int px = sx + 2 * pp + e;
            #pragma unroll
            for (int q = 0; q < 4; q++) {
                float r[3];
                #pragma unroll
                for (int o = 0; o < 3; o++) {
                    float a, bv; unpack2(acc[o][q][pp], a, bv);
                    const float v = e ? bv : a;
                    r[o] = 1.0f / (1.0f + __expf(-v));
                }
                const int qa = q >> 1, qb = q & 1;
                g4[(2 * sy + qa) * DS + 2 * px + qb] = make_float4(r[0], r[1], r[2], 0.0f);
            }
        }
    }
}

// ---------------------------------------------------------------------------
// Kernel 1: decode 160 objects (block = object). Redundant per-block top-3.
// ---------------------------------------------------------------------------
__global__ void __launch_bounds__(256, 2) decode_kernel(
    const float* __restrict__ z_depth,
    const float* __restrict__ z_what,
    const float* __restrict__ W0, const float* __restrict__ b0,
    const float* __restrict__ W1, const float* __restrict__ b1,
    const float* __restrict__ W2, const float* __restrict__ b2,
    const float* __restrict__ W3, const float* __restrict__ b3,
    const float* __restrict__ W4, const float* __restrict__ b4,
    const float* __restrict__ W5, const float* __restrict__ b5)
{
    extern __shared__ float sm[];
    float* bufA = sm;           // up to 8192 floats
    float* bufB = sm + 8192;    // up to 16384 floats

    const int m = blockIdx.x;
    const int b = m / TOPK;
    const int j = m % TOPK;

    const int ord = block_topk(z_depth, b, j, bufB);
    if (threadIdx.x == 0) g_order[m] = ord;

    const int loc = prior_to_loc(ord);
    const float* src = z_what + (size_t)(b * NLOC + loc) * ZWHAT;
    if (threadIdx.x < ZWHAT) bufA[threadIdx.x] = src[threadIdx.x];
    __syncthreads();

    dlayer_t< 64, 256,  1,  1, 8>(bufA, bufB, W0, b0); __syncthreads(); // 256x2x2
    dlayer_t<256, 128,  2,  2, 8>(bufB, bufA, W1, b1); __syncthreads(); // 128x4x4
    dlayer_t<128,  64,  4,  4, 8>(bufA, bufB, W2, b2); __syncthreads(); // 64x8x8
    dlayer_t< 64,  32,  8,  8, 4>(bufB, bufA, W3, b3); __syncthreads(); // 32x16x16
    dlayer_t< 32,  16, 16, 16, 2>(bufA, bufB, W4, b4); __syncthreads(); // 16x32x32

    // stage W5 + b5 into (now free) bufA, then final layer bufB -> global
    if (threadIdx.x < 192) bufA[threadIdx.x] = W5[threadIdx.x];
    if (threadIdx.x < 3)   bufA[192 + threadIdx.x] = b5[threadIdx.x];
    __syncthreads();
    final_layer(bufB, bufA, g_decoded + (size_t)m * CPAD * DS * DS);
}

// ---------------------------------------------------------------------------
// Kernel 2: fused STN + depth-ordered first-nonzero compositing, 16x16 tiles
// with conservative per-tile object culling (exact per-pixel test unchanged).
// ---------------------------------------------------------------------------
__global__ void __launch_bounds__(256) composite_kernel(
    const float* __restrict__ z_where,
    const int*   __restrict__ z_present,
    float* __restrict__ out)
{
    const int b = blockIdx.y;
    const int tx0 = (blockIdx.x % NTX) * TILE;
    const int ty0 = (blockIdx.x / NTX) * TILE;

    __shared__ float s_sx[TOPK], s_ox[TOPK], s_sy[TOPK], s_oy[TOPK];
    __shared__ int   s_flag[TOPK];
    __shared__ int   s_list[TOPK];
    __shared__ int   s_nc;

    const int tid = threadIdx.x;
    if (tid < TOPK) {
        const int ord = g_order[b * TOPK + tid];
        const float* zw = z_where + (size_t)(b * NPRI + ord) * 4;
        const float cx = zw[0], cy = zw[1];
        const float w = zw[2] + 1e-6f, h = zw[3] + 1e-6f;
        const float half = (float)DS * 0.5f;   // 32
        const float xsn = half / w;
        const float ysn = half / h;
        const float sx = xsn * (2.0f / (float)IMG);
        const float ox = half - 0.5f
                         + xsn * ((1.0f / (float)IMG - 1.0f) - (2.0f * cx - 1.0f));
        const float sy = ysn * (2.0f / (float)IMG);
        const float oy = half - 0.5f
                         + ysn * ((1.0f / (float)IMG - 1.0f) - (2.0f * cy - 1.0f));
        s_sx[tid] = sx; s_ox[tid] = ox; s_sy[tid] = sy; s_oy[tid] = oy;
        const float ix_lo = fmaf((float)tx0, sx, ox);
        const float ix_hi = fmaf((float)(tx0 + TILE - 1), sx, ox);
        const float iy_lo = fmaf((float)ty0, sy, oy);
        const float iy_hi = fmaf((float)(ty0 + TILE - 1), sy, oy);
        const bool pres = (z_present[b * NPRI + ord] == 1);
        s_flag[tid] = (pres &&
                       ix_hi >= -1.01f && ix_lo < 64.01f &&
                       iy_hi >= -1.01f && iy_lo < 64.01f) ? 1 : 0;
    }
    __syncthreads();
    if (tid == 0) {
        int nc = 0;
        #pragma unroll
        for (int k = 0; k < TOPK; k++)
            if (s_flag[k]) s_list[nc++] = k;   // preserves depth order
        s_nc = nc;
    }
    __syncthreads();

    const int x = tx0 + (tid % TILE);
    const int y = ty0 + (tid / TILE);
    if (x >= IMG || y >= IMG) return;
    const float fx = (float)x, fy = (float)y;

    float r0 = 0.0f, r1 = 0.0f, r2 = 0.0f;
    int done = 0;
    const int nc = s_nc;

    for (int kk = 0; kk < nc; kk++) {
        const int k = s_list[kk];
        const float ix = fmaf(fx, s_sx[k], s_ox[k]);
        const float iy = fmaf(fy, s_sy[k], s_oy[k]);
        const float ix0f = floorf(ix), iy0f = floorf(iy);
        if (!(ix0f >= -1.0f && ix0f <= 63.0f && iy0f >= -1.0f && iy0f <= 63.0f))
            continue;   // sample exactly zero -> never "first"
        const float wx1 = ix - ix0f, wy1 = iy - iy0f;
        const float wx0 = 1.0f - wx1, wy0 = 1.0f - wy1;
        const int ix0 = (int)ix0f, iy0 = (int)iy0f;
        const bool vx0 = (ix0 >= 0), vx1 = (ix0 <= 62);
        const bool vy0 = (iy0 >= 0), vy1 = (iy0 <= 62);
        const float w00 = (vy0 && vx0) ? wy0 * wx0 : 0.0f;
        const float w01 = (vy0 && vx1) ? wy0 * wx1 : 0.0f;
        const float w10 = (vy1 && vx0) ? wy1 * wx0 : 0.0f;
        const float w11 = (vy1 && vx1) ? wy1 * wx1 : 0.0f;
        const int x0c = max(ix0, 0),     x1c = min(ix0 + 1, DS - 1);
        const int y0c = max(iy0, 0),     y1c = min(iy0 + 1, DS - 1);
        const int i00 = y0c * DS + x0c, i01 = y0c * DS + x1c;
        const int i10 = y1c * DS + x0c, i11 = y1c * DS + x1c;
        const float4* __restrict__ base = reinterpret_cast<const float4*>(g_decoded)
                                          + (size_t)(b * TOPK + k) * DS * DS;
        const float4 t00 = __ldg(base + i00);
        const float4 t01 = __ldg(base + i01);
        const float4 t10 = __ldg(base + i10);
        const float4 t11 = __ldg(base + i11);

        const float s0 = t00.x * w00 + t01.x * w01 + t10.x * w10 + t11.x * w11;
        const float s1 = t00.y * w00 + t01.y * w01 + t10.y * w10 + t11.y * w11;
        const float s2 = t00.z * w00 + t01.z * w01 + t10.z * w10 + t11.z * w11;

        if (!(done & 1) && s0 != 0.0f) { r0 = s0; done |= 1; }
        if (!(done & 2) && s1 != 0.0f) { r1 = s1; done |= 2; }
        if (!(done & 4) && s2 != 0.0f) { r2 = s2; done |= 4; }
        if (done == 7) break;
    }

    const size_t pix = (size_t)y * IMG + x;
    out[((size_t)(b * 3 + 0) * IMG * IMG) + pix] = r0;
    out[((size_t)(b * 3 + 1) * IMG * IMG) + pix] = r1;
    out[((size_t)(b * 3 + 2) * IMG * IMG) + pix] = r2;
}

// ---------------------------------------------------------------------------
extern "C" void kernel_launch(void* const* d_in, const int* in_sizes, int n_in,
                              void* d_out, int out_size)
{
    const float* z_what    = (const float*)d_in[0];
    const float* z_where   = (const float*)d_in[1];
    const int*   z_present = (const int*)  d_in[2];
    const float* z_depth   = (const float*)d_in[3];
    const float* W0 = (const float*)d_in[4];  const float* b0 = (const float*)d_in[5];
    const float* W1 = (const float*)d_in[6];  const float* b1 = (const float*)d_in[7];
    const float* W2 = (const float*)d_in[8];  const float* b2 = (const float*)d_in[9];
    const float* W3 = (const float*)d_in[10]; const float* b3 = (const float*)d_in[11];
    const float* W4 = (const float*)d_in[12]; const float* b4 = (const float*)d_in[13];
    const float* W5 = (const float*)d_in[14]; const float* b5 = (const float*)d_in[15];
    float* out = (float*)d_out;

    static bool attr_set = false;
    if (!attr_set) {
        cudaFuncSetAttribute(decode_kernel,
                             cudaFuncAttributeMaxDynamicSharedMemorySize,
                             (8192 + 16384) * sizeof(float));
        attr_set = true;
    }

    decode_kernel<<<NOBJ, 256, (8192 + 16384) * sizeof(float)>>>(
        z_depth, z_what, W0, b0, W1, b1, W2, b2, W3, b3, W4, b4, W5, b5);

    dim3 cgrid(NTX * NTX, BATCH);
    composite_kernel<<<cgrid, 256>>>(z_where, z_present, out);
}